// round 2
// baseline (speedup 1.0000x reference)
#include <cuda_runtime.h>
#include <cuda_bf16.h>
#include <cstdint>

typedef unsigned long long ull;

#define VV 32000
#define EE 32
#define HH 128
#define BB 2
#define TT 512
#define RR (BB*TT)                       // 1024
#define OFF_HID (RR*VV)                  // 32768000
#define OFF_W   (OFF_HID + BB*HH)        // 32768256

// ---------------- scratch (static device globals; no allocation) ----------------
__device__ float g_xp [RR*HH];
__device__ float g_rnn[RR*HH];
__device__ float g_q  [RR*HH];
__device__ float g_k  [RR*HH];
__device__ float g_ctx[RR*HH];
__device__ float g_prj[RR*HH];
__device__ int   g_x64;

// ---------------- helpers ----------------
__device__ __forceinline__ void fma2(ull &d, ull a, ull b) {
    asm("fma.rn.f32x2 %0, %1, %2, %0;" : "+l"(d) : "l"(a), "l"(b));
}
__device__ __forceinline__ ull pack2(float a, float b) {
    ull r;
    asm("mov.b64 %0, {%1, %2};" : "=l"(r) : "r"(__float_as_uint(a)), "r"(__float_as_uint(b)));
    return r;
}
__device__ __forceinline__ float ull_lo(ull u){ return __uint_as_float((unsigned)(u & 0xffffffffull)); }
__device__ __forceinline__ float ull_hi(ull u){ return __uint_as_float((unsigned)(u >> 32)); }

// accurate-enough tanh: 2 MUFU (EX2 + RCP), rel err ~1e-6, robust at +-inf
__device__ __forceinline__ float tanh_fast(float x) {
    float e = __expf(2.0f * x);
    return 1.0f - __fdividef(2.0f, e + 1.0f);
}

// ---------------- K0: detect int64 vs int32 ids ----------------
__global__ void detect_kernel(const int* __restrict__ x32) {
    __shared__ int bad;
    if (threadIdx.x == 0) bad = 0;
    __syncthreads();
    for (int i = threadIdx.x; i < 512; i += blockDim.x)
        if (x32[2*i + 1] != 0) atomicExch(&bad, 1);
    __syncthreads();
    if (threadIdx.x == 0) g_x64 = bad ? 0 : 1;
}

// ---------------- K1: embedding + input projection (xp = emb@W_ih^T + b_ih + b_hh) ----------------
__global__ void embed_kernel(const int* __restrict__ x32,
                             const float* __restrict__ et,
                             const float* __restrict__ W_ih,
                             const float* __restrict__ b_ih,
                             const float* __restrict__ b_hh) {
    __shared__ float e_sh[EE];
    __shared__ float Wsh[HH * 33];
    int r = blockIdx.x;
    int h = threadIdx.x;
    for (int j = h; j < HH * EE; j += HH) {
        int hh = j >> 5, ee = j & 31;
        Wsh[hh * 33 + ee] = W_ih[j];
    }
    int id = g_x64 ? x32[2 * r] : x32[r];
    if (h < EE) e_sh[h] = et[id * EE + h];
    __syncthreads();
    float acc = b_ih[h] + b_hh[h];
#pragma unroll
    for (int e = 0; e < EE; e++) acc += Wsh[h * 33 + e] * e_sh[e];
    g_xp[r * HH + h] = acc;
}

// ---------------- K2: sequential RNN scan (1 block per batch, W_hh in registers) ----------------
__global__ void rnn_kernel(const float* __restrict__ hidden,
                           const float* __restrict__ W_hh,
                           float* __restrict__ out_hid) {
    __shared__ __align__(16) float h_sh[2][HH];
    int b = blockIdx.x;
    int tid = threadIdx.x;
    int h = tid >> 2, part = tid & 3;

    // preload W_hh[h][part*32 .. part*32+31] into 16 packed f32x2 regs
    ull w2[16];
    {
        const ulonglong2* wp = (const ulonglong2*)(W_hh + h * HH + part * 32);
#pragma unroll
        for (int i = 0; i < 8; i++) { ulonglong2 v = wp[i]; w2[2*i] = v.x; w2[2*i+1] = v.y; }
    }
    if (tid < HH) h_sh[0][tid] = hidden[b * HH + tid];
    __syncthreads();

    const float* xpb = g_xp + b * TT * HH;
    float* rnnb = g_rnn + b * TT * HH;

    for (int t = 0; t < TT; t++) {
        int cur = t & 1;
        const ulonglong2* hp = (const ulonglong2*)(&h_sh[cur][part * 32]);
        ull a0 = 0ull, a1 = 0ull;
#pragma unroll
        for (int i = 0; i < 8; i++) {
            ulonglong2 hh2 = hp[i];
            fma2(a0, w2[2*i],   hh2.x);
            fma2(a1, w2[2*i+1], hh2.y);
        }
        float s = ull_lo(a0) + ull_hi(a0) + ull_lo(a1) + ull_hi(a1);
        s += __shfl_xor_sync(0xffffffffu, s, 1);
        s += __shfl_xor_sync(0xffffffffu, s, 2);
        if (part == 0) {
            float hn = tanh_fast(xpb[t * HH + h] + s);
            h_sh[cur ^ 1][h] = hn;
            rnnb[t * HH + h] = hn;
        }
        __syncthreads();
    }
    if (part == 0) out_hid[b * HH + h] = h_sh[0][h];
}

// ---------------- K3: q = rnn@W1^T, k = rnn@W2^T ----------------
__global__ void qk_kernel(const float* __restrict__ W1, const float* __restrict__ W2) {
    __shared__ float Wc[2][HH * 33];
    __shared__ float rsh[16 * 33];
    int bx = blockIdx.x;
    int b = bx >> 5, tc = bx & 31;
    int tid = threadIdx.x;
    int wsel = tid >> 7, h = tid & 127;
    float acc[16];
#pragma unroll
    for (int i = 0; i < 16; i++) acc[i] = 0.f;

    for (int kc = 0; kc < HH; kc += 32) {
        __syncthreads();
        for (int j = tid; j < 2 * HH * 32; j += 256) {
            int ws = j >> 12; int rem = j & 4095;
            int hh = rem >> 5, kk = rem & 31;
            Wc[ws][hh * 33 + kk] = (ws ? W2 : W1)[hh * HH + kc + kk];
        }
        for (int j = tid; j < 16 * 32; j += 256) {
            int tt = j >> 5, kk = j & 31;
            rsh[tt * 33 + kk] = g_rnn[(b * TT + tc * 16 + tt) * HH + kc + kk];
        }
        __syncthreads();
#pragma unroll
        for (int kk = 0; kk < 32; kk++) {
            float w = Wc[wsel][h * 33 + kk];
#pragma unroll
            for (int tt = 0; tt < 16; tt++) acc[tt] += w * rsh[tt * 33 + kk];
        }
    }
    float* dst = wsel ? g_k : g_q;
    for (int tt = 0; tt < 16; tt++)
        dst[(b * TT + tc * 16 + tt) * HH + h] = acc[tt];
}

// ---------------- K4: additive attention (scores, softmax, weights out, context) ----------------
__global__ void attn_kernel(const float* __restrict__ v, float* __restrict__ wout) {
    __shared__ float q_sh[HH], v_sh[HH];
    __shared__ float ksh[64 * 132];
    __shared__ float sc[TT];
    __shared__ float red[8];
    __shared__ float redval;
    __shared__ float ctxp[HH];

    int bx = blockIdx.x;
    int b = bx >> 9, t = bx & 511;
    int tid = threadIdx.x;
    int r = b * TT + t;
    int n = t + 1;

    if (tid < HH) { q_sh[tid] = g_q[r * HH + tid]; v_sh[tid] = v[tid]; }
    __syncthreads();

    int sl = tid >> 2, qq = tid & 3;
    for (int s0 = 0; s0 < n; s0 += 64) {
        int cnt = min(64, n - s0);
        __syncthreads();
        for (int j = tid; j < cnt * HH; j += 256) {
            int ss = j >> 7, hh = j & 127;
            ksh[ss * 132 + hh] = g_k[(b * TT + s0 + ss) * HH + hh];
        }
        __syncthreads();
        // compute score for (t, s0+sl); shuffles must be warp-convergent,
        // so compute unconditionally (acc=0 for out-of-range sl) and
        // predicate only the store. XOR 1/2 stays within one sl's quad.
        float acc = 0.f;
        if (sl < cnt) {
            const float* kr = &ksh[sl * 132];
#pragma unroll 8
            for (int i = 0; i < 32; i++) {
                int hh = qq + 4 * i;
                acc += v_sh[hh] * tanh_fast(q_sh[hh] + kr[hh]);
            }
        }
        acc += __shfl_xor_sync(0xffffffffu, acc, 1);
        acc += __shfl_xor_sync(0xffffffffu, acc, 2);
        if (qq == 0 && sl < cnt) sc[s0 + sl] = acc;
    }
    __syncthreads();

    // softmax over sc[0..n)
    float m = -1e30f;
    for (int s = tid; s < n; s += 256) m = fmaxf(m, sc[s]);
#pragma unroll
    for (int o = 16; o; o >>= 1) m = fmaxf(m, __shfl_xor_sync(0xffffffffu, m, o));
    if ((tid & 31) == 0) red[tid >> 5] = m;
    __syncthreads();
    if (tid == 0) {
        float mm = red[0];
#pragma unroll
        for (int i = 1; i < 8; i++) mm = fmaxf(mm, red[i]);
        redval = mm;
    }
    __syncthreads();
    m = redval;

    float ssum = 0.f;
    for (int s = tid; s < n; s += 256) {
        float e = __expf(sc[s] - m);
        sc[s] = e;
        ssum += e;
    }
#pragma unroll
    for (int o = 16; o; o >>= 1) ssum += __shfl_xor_sync(0xffffffffu, ssum, o);
    __syncthreads();
    if ((tid & 31) == 0) red[tid >> 5] = ssum;
    __syncthreads();
    if (tid == 0) {
        float s2 = 0.f;
#pragma unroll
        for (int i = 0; i < 8; i++) s2 += red[i];
        redval = s2;
    }
    __syncthreads();
    float inv = __fdividef(1.0f, redval);

    for (int s = tid; s < TT; s += 256) {
        float w = (s < n) ? sc[s] * inv : 0.f;
        if (s < n) sc[s] = w;
        wout[(size_t)r * TT + s] = w;
    }
    __syncthreads();

    // context: ctx[h] = sum_s w[s] * rnn[b,s,h]
    int h = tid & 127, g = tid >> 7;
    float acc = 0.f;
    for (int s = g; s < n; s += 2)
        acc += sc[s] * g_rnn[(b * TT + s) * HH + h];
    if (g == 1) ctxp[h] = acc;
    __syncthreads();
    if (g == 0) g_ctx[r * HH + h] = acc + ctxp[h];
}

// ---------------- K5: out = relu([rnn|ctx] @ Wp^T + bp) ----------------
__global__ void proj_kernel(const float* __restrict__ Wp, const float* __restrict__ bp) {
    __shared__ float comb[16 * 256];
    __shared__ float Wsh[HH * 33];
    int bx = blockIdx.x;
    int b = bx >> 5, tc = bx & 31;
    int tid = threadIdx.x;
    int h = tid & 127, g = tid >> 7;
    int rbase = b * TT + tc * 16;

    for (int j = tid; j < 16 * HH; j += 256) {
        int tt = j >> 7, k = j & 127;
        comb[tt * 256 + k]        = g_rnn[(rbase + tt) * HH + k];
        comb[tt * 256 + 128 + k]  = g_ctx[(rbase + tt) * HH + k];
    }
    float acc[8];
#pragma unroll
    for (int i = 0; i < 8; i++) acc[i] = 0.f;

    for (int kc = 0; kc < 256; kc += 32) {
        __syncthreads();
        for (int j = tid; j < HH * 32; j += 256) {
            int hh = j >> 5, kk = j & 31;
            Wsh[hh * 33 + kk] = Wp[hh * 256 + kc + kk];
        }
        __syncthreads();
#pragma unroll
        for (int kk = 0; kk < 32; kk++) {
            float w = Wsh[h * 33 + kk];
#pragma unroll
            for (int tt = 0; tt < 8; tt++)
                acc[tt] += w * comb[(g * 8 + tt) * 256 + kc + kk];
        }
    }
    float bb = bp[h];
#pragma unroll
    for (int tt = 0; tt < 8; tt++) {
        float o = fmaxf(acc[tt] + bb, 0.f);
        g_prj[(rbase + g * 8 + tt) * HH + h] = o;
    }
}

// ---------------- K6: logits = prj @ Wfc^T + bfc  (fp32, packed f32x2 FMA) ----------------
// tile: 64 rows x 128 vocab, K=128. thread micro-tile: 4 vocab x 8 rows (4 row-pairs).
__global__ void logits_kernel(const float* __restrict__ Wfc,
                              const float* __restrict__ bfc,
                              float* __restrict__ out) {
    extern __shared__ float sm[];
    float* As = sm;                 // [k][r] 128 x 68 (pad)
    float* Ws = sm + 128 * 68;      // [k][v] 128 x 132 (pad)
    int vbase = blockIdx.x * 128;
    int rbase = blockIdx.y * 64;
    int tid = threadIdx.x;

    const float4* A4 = (const float4*)g_prj;
    for (int j = tid; j < 64 * 32; j += 256) {
        int r = j >> 5, k4 = j & 31;
        float4 f = A4[(size_t)(rbase + r) * 32 + k4];
        int k = k4 * 4;
        As[(k + 0) * 68 + r] = f.x;
        As[(k + 1) * 68 + r] = f.y;
        As[(k + 2) * 68 + r] = f.z;
        As[(k + 3) * 68 + r] = f.w;
    }
    const float4* W4 = (const float4*)Wfc;
    for (int j = tid; j < 128 * 32; j += 256) {
        int vv = j >> 5, k4 = j & 31;
        float4 f = W4[(size_t)(vbase + vv) * 32 + k4];
        int k = k4 * 4;
        Ws[(k + 0) * 132 + vv] = f.x;
        Ws[(k + 1) * 132 + vv] = f.y;
        Ws[(k + 2) * 132 + vv] = f.z;
        Ws[(k + 3) * 132 + vv] = f.w;
    }
    __syncthreads();

    int tv = tid & 31, tr = tid >> 5;
    int r0 = tr * 8, v0 = tv * 4;

    ull acc[4][4];
#pragma unroll
    for (int i = 0; i < 4; i++)
#pragma unroll
        for (int p = 0; p < 4; p++) acc[i][p] = 0ull;

#pragma unroll 4
    for (int k = 0; k < 128; k++) {
        ulonglong2 a01 = *(const ulonglong2*)&As[k * 68 + r0];
        ulonglong2 a23 = *(const ulonglong2*)&As[k * 68 + r0 + 4];
        float4 w = *(const float4*)&Ws[k * 132 + v0];
        ull wd0 = pack2(w.x, w.x);
        ull wd1 = pack2(w.y, w.y);
        ull wd2 = pack2(w.z, w.z);
        ull wd3 = pack2(w.w, w.w);
        fma2(acc[0][0], wd0, a01.x); fma2(acc[0][1], wd0, a01.y);
        fma2(acc[0][2], wd0, a23.x); fma2(acc[0][3], wd0, a23.y);
        fma2(acc[1][0], wd1, a01.x); fma2(acc[1][1], wd1, a01.y);
        fma2(acc[1][2], wd1, a23.x); fma2(acc[1][3], wd1, a23.y);
        fma2(acc[2][0], wd2, a01.x); fma2(acc[2][1], wd2, a01.y);
        fma2(acc[2][2], wd2, a23.x); fma2(acc[2][3], wd2, a23.y);
        fma2(acc[3][0], wd3, a01.x); fma2(acc[3][1], wd3, a01.y);
        fma2(acc[3][2], wd3, a23.x); fma2(acc[3][3], wd3, a23.y);
    }

    float4 bb = *(const float4*)&bfc[vbase + v0];
#pragma unroll
    for (int p = 0; p < 4; p++) {
        int row0 = rbase + r0 + 2 * p;
        float4 o0, o1;
        o0.x = ull_lo(acc[0][p]) + bb.x; o1.x = ull_hi(acc[0][p]) + bb.x;
        o0.y = ull_lo(acc[1][p]) + bb.y; o1.y = ull_hi(acc[1][p]) + bb.y;
        o0.z = ull_lo(acc[2][p]) + bb.z; o1.z = ull_hi(acc[2][p]) + bb.z;
        o0.w = ull_lo(acc[3][p]) + bb.w; o1.w = ull_hi(acc[3][p]) + bb.w;
        *(float4*)&out[(size_t)row0 * VV + vbase + v0]       = o0;
        *(float4*)&out[(size_t)(row0 + 1) * VV + vbase + v0] = o1;
    }
}

// ---------------- launch ----------------
extern "C" void kernel_launch(void* const* d_in, const int* in_sizes, int n_in,
                              void* d_out, int out_size) {
    const int*   x32    = (const int*)  d_in[0];
    const float* hidden = (const float*)d_in[1];
    const float* et     = (const float*)d_in[2];
    const float* W_ih   = (const float*)d_in[3];
    const float* W_hh   = (const float*)d_in[4];
    const float* b_ih   = (const float*)d_in[5];
    const float* b_hh   = (const float*)d_in[6];
    const float* W1     = (const float*)d_in[7];
    const float* W2     = (const float*)d_in[8];
    const float* v      = (const float*)d_in[9];
    const float* Wp     = (const float*)d_in[10];
    const float* bp     = (const float*)d_in[11];
    const float* Wfc    = (const float*)d_in[12];
    const float* bfc    = (const float*)d_in[13];
    float* out = (float*)d_out;

    cudaFuncSetAttribute(logits_kernel, cudaFuncAttributeMaxDynamicSharedMemorySize, 102400);

    detect_kernel<<<1, 256>>>(x32);
    embed_kernel<<<RR, HH>>>(x32, et, W_ih, b_ih, b_hh);
    rnn_kernel<<<BB, 512>>>(hidden, W_hh, out + OFF_HID);
    qk_kernel<<<64, 256>>>(W1, W2);
    attn_kernel<<<RR, 256>>>(v, out + OFF_W);
    proj_kernel<<<64, 256>>>(Wp, bp);
    logits_kernel<<<dim3(VV / 128, RR / 64), 256, 102400>>>(Wfc, bfc, out);
}